// round 1
// baseline (speedup 1.0000x reference)
#include <cuda_runtime.h>

// CARAFE: features [2,64,64,256] f32, masks [2,128,128,25] f32, k=5, group=1.
// Nearest 64->128 with half-pixel centers => src = dst >> 1.
// out[b, 2*hs+oy, 2*ws+ox, c] = sum_p mask[b,2*hs+oy,2*ws+ox,p] * feat[b, hs-2+p/5, ws-2+p%5, c]
// (zero-padded outside the 64x64 feature map).

#define FH 64
#define FW 64
#define CH 256
#define C4 64      // CH / 4 (float4 groups)
#define OH 128
#define OW 128
#define KK 25
#define SEGW 8     // source columns per block

__device__ __forceinline__ void fma4(float4& a, const float4 f, const float m) {
    a.x = fmaf(f.x, m, a.x);
    a.y = fmaf(f.y, m, a.y);
    a.z = fmaf(f.z, m, a.z);
    a.w = fmaf(f.w, m, a.w);
}

__global__ __launch_bounds__(64)
void carafe_kernel(const float* __restrict__ features,
                   const float* __restrict__ masks,
                   float* __restrict__ out)
{
    // smask layout: [px(8)][tap(25)][out(4)]  (out = oy*2+ox), float4-readable per tap
    __shared__ __align__(16) float smask[SEGW * KK * 4];

    const int tid = threadIdx.x;
    const int seg = blockIdx.x;
    const int hs  = blockIdx.y;
    const int b   = blockIdx.z;
    const int ws0 = seg * SEGW;

    // ---- cooperative mask load: 2 output rows x 16 output cols x 25 taps = 800 floats ----
    {
        const int mrow0 = ((b * OH + 2 * hs    ) * OW + 2 * ws0) * KK;
        const int mrow1 = ((b * OH + 2 * hs + 1) * OW + 2 * ws0) * KK;
        #pragma unroll
        for (int it = 0; it < 13; it++) {
            int idx = tid + it * 64;
            if (idx < 800) {
                int oy   = idx / 400;          // 0..1
                int j    = idx - oy * 400;     // 0..399 contiguous within the global mask row
                int wrel = j / KK;             // 0..15 output col within segment
                int p    = j - wrel * KK;      // tap
                int px   = wrel >> 1;          // source col within segment
                int ox   = wrel & 1;
                float v = masks[(oy ? mrow1 : mrow0) + j];
                smask[px * (KK * 4) + p * 4 + oy * 2 + ox] = v;
            }
        }
    }
    __syncthreads();

    const float4* __restrict__ F = (const float4*)features;
    const int c4 = tid;  // this thread's float4 channel group

    bool rowok[5];
    int  rowbase[5];
    #pragma unroll
    for (int r = 0; r < 5; r++) {
        int hr = hs - 2 + r;
        rowok[r]   = (hr >= 0) && (hr < FH);
        rowbase[r] = ((b * FH + hr) * FW) * C4 + c4;
    }

    // ---- rolling 5x5 float4 register window; full unroll => shifts are free renames ----
    float4 win[5][5];
    #pragma unroll
    for (int cc = 0; cc < 5; cc++) {
        int wc = ws0 - 2 + cc;
        bool colok = (wc >= 0) && (wc < FW);
        #pragma unroll
        for (int r = 0; r < 5; r++) {
            win[r][cc] = (rowok[r] && colok) ? F[rowbase[r] + wc * C4]
                                             : make_float4(0.f, 0.f, 0.f, 0.f);
        }
    }

    float4* __restrict__ O = (float4*)out;

    #pragma unroll
    for (int s = 0; s < SEGW; s++) {
        const int ws = ws0 + s;
        const float4* __restrict__ mp = (const float4*)&smask[s * (KK * 4)];

        float4 a0 = make_float4(0.f, 0.f, 0.f, 0.f);
        float4 a1 = a0, a2 = a0, a3 = a0;

        #pragma unroll
        for (int p = 0; p < KK; p++) {
            const float4 f = win[p / 5][p % 5];
            const float4 m = mp[p];            // broadcast LDS.128: masks for 4 outputs at tap p
            fma4(a0, f, m.x);                  // (oy=0, ox=0)
            fma4(a1, f, m.y);                  // (oy=0, ox=1)
            fma4(a2, f, m.z);                  // (oy=1, ox=0)
            fma4(a3, f, m.w);                  // (oy=1, ox=1)
        }

        const int ob0 = ((b * OH + 2 * hs    ) * OW + 2 * ws) * C4 + c4;
        const int ob1 = ((b * OH + 2 * hs + 1) * OW + 2 * ws) * C4 + c4;
        O[ob0]      = a0;
        O[ob0 + C4] = a1;
        O[ob1]      = a2;
        O[ob1 + C4] = a3;

        if (s < SEGW - 1) {
            // shift window left by one column (compile-time renaming after unroll)
            #pragma unroll
            for (int r = 0; r < 5; r++) {
                win[r][0] = win[r][1];
                win[r][1] = win[r][2];
                win[r][2] = win[r][3];
                win[r][3] = win[r][4];
            }
            const int wc = ws + 3;          // always > 0 here
            const bool colok = (wc < FW);
            #pragma unroll
            for (int r = 0; r < 5; r++) {
                win[r][4] = (rowok[r] && colok) ? F[rowbase[r] + wc * C4]
                                                : make_float4(0.f, 0.f, 0.f, 0.f);
            }
        }
    }
}

extern "C" void kernel_launch(void* const* d_in, const int* in_sizes, int n_in,
                              void* d_out, int out_size) {
    const float* features = (const float*)d_in[0];
    const float* masks    = (const float*)d_in[1];
    float* out            = (float*)d_out;

    dim3 grid(FW / SEGW, FH, 2);   // (8, 64, 2) = 1024 blocks
    carafe_kernel<<<grid, 64>>>(features, masks, out);
}